// round 1
// baseline (speedup 1.0000x reference)
#include <cuda_runtime.h>
#include <math.h>

// ---------------- scratch (device globals; no allocation allowed) ----------
#define MAXN 50000
#define MAXE 800000
#define NG   128
#define INF_ 128
#define HID  64
#define OUTF 32

__device__ float g_deg[MAXN];
__device__ float g_dinv[MAXN];
__device__ float g_h[(size_t)MAXN * HID];    // x @ W
__device__ float g_acc[(size_t)MAXN * HID];  // aggregated messages
__device__ float g_sums[NG * HID];
__device__ float g_cnt[NG];
__device__ int   g_is64;

// ---------------- kernels ---------------------------------------------------

__global__ void k_init(int N) {
    int total = N * HID;
    for (int i = blockIdx.x * blockDim.x + threadIdx.x; i < total;
         i += gridDim.x * blockDim.x) {
        g_acc[i] = 0.0f;
        if (i < N)        g_deg[i]  = 1.0f;   // self-loop weight
        if (i < NG * HID) g_sums[i] = 0.0f;
        if (i < NG)       g_cnt[i]  = 0.0f;
    }
}

// Detect whether edge_index is int64 (high 32-bit words all zero) or int32.
// Safe: reads only first 1.6M int32 words (valid under both interpretations).
__global__ void k_detect(const int* __restrict__ ei_w, int E) {
    __shared__ int any_nonzero;
    if (threadIdx.x == 0) any_nonzero = 0;
    __syncthreads();
    // check 1024 odd words (would be int64 high halves)
    for (int i = threadIdx.x; i < 1024; i += blockDim.x) {
        if (ei_w[2 * i + 1] != 0) atomicOr(&any_nonzero, 1);
    }
    __syncthreads();
    if (threadIdx.x == 0) g_is64 = any_nonzero ? 0 : 1;
}

__device__ __forceinline__ int load_idx(const void* p, long long i) {
    if (g_is64) return (int)((const long long*)p)[i];
    return ((const int*)p)[i];
}

__global__ void k_deg(const void* __restrict__ ei, const float* __restrict__ ew,
                      int E) {
    int e = blockIdx.x * blockDim.x + threadIdx.x;
    if (e >= E) return;
    int d = load_idx(ei, (long long)E + e);
    atomicAdd(&g_deg[d], ew[e]);
}

__global__ void k_dinv(int N) {
    int n = blockIdx.x * blockDim.x + threadIdx.x;
    if (n >= N) return;
    float dg = g_deg[n];
    g_dinv[n] = dg > 0.0f ? rsqrtf(dg) : 0.0f;
}

// h = x @ W  (x: [N,128], W: [128,64]) -> g_h [N,64]
// Block: 256 threads computes 64 rows x 64 cols; 4x4 register tile/thread.
__global__ __launch_bounds__(256) void k_gemm1(const float* __restrict__ x,
                                               const float* __restrict__ W,
                                               int N) {
    __shared__ float xs[64][132];      // padded vs bank conflicts
    __shared__ float Ws[128][64];
    const int t = threadIdx.x;
    const int row0 = blockIdx.x * 64;

    // load W (128x64 = 2048 float4)
    for (int i = t; i < 2048; i += 256) {
        int k = i >> 4, c4 = i & 15;
        *(float4*)&Ws[k][c4 * 4] = ((const float4*)W)[i];
    }
    // load 64 rows of x (each row 32 float4)
    for (int i = t; i < 64 * 32; i += 256) {
        int r = i >> 5, k4 = i & 31;
        float4 v = make_float4(0.f, 0.f, 0.f, 0.f);
        if (row0 + r < N) v = ((const float4*)(x + (size_t)(row0 + r) * INF_))[k4];
        xs[r][k4 * 4 + 0] = v.x; xs[r][k4 * 4 + 1] = v.y;
        xs[r][k4 * 4 + 2] = v.z; xs[r][k4 * 4 + 3] = v.w;
    }
    __syncthreads();

    const int ty = t >> 4, tx = t & 15;
    float acc[4][4];
#pragma unroll
    for (int i = 0; i < 4; i++)
#pragma unroll
        for (int j = 0; j < 4; j++) acc[i][j] = 0.0f;

#pragma unroll 4
    for (int k = 0; k < 128; k++) {
        float a0 = xs[ty * 4 + 0][k];
        float a1 = xs[ty * 4 + 1][k];
        float a2 = xs[ty * 4 + 2][k];
        float a3 = xs[ty * 4 + 3][k];
        float4 w = *(float4*)&Ws[k][tx * 4];
        acc[0][0] += a0 * w.x; acc[0][1] += a0 * w.y; acc[0][2] += a0 * w.z; acc[0][3] += a0 * w.w;
        acc[1][0] += a1 * w.x; acc[1][1] += a1 * w.y; acc[1][2] += a1 * w.z; acc[1][3] += a1 * w.w;
        acc[2][0] += a2 * w.x; acc[2][1] += a2 * w.y; acc[2][2] += a2 * w.z; acc[2][3] += a2 * w.w;
        acc[3][0] += a3 * w.x; acc[3][1] += a3 * w.y; acc[3][2] += a3 * w.z; acc[3][3] += a3 * w.w;
    }
#pragma unroll
    for (int i = 0; i < 4; i++) {
        int row = row0 + ty * 4 + i;
        if (row < N) {
            float4 v = make_float4(acc[i][0], acc[i][1], acc[i][2], acc[i][3]);
            *(float4*)(g_h + (size_t)row * HID + tx * 4) = v;
        }
    }
}

// Per (edge, quarter): 16 threads handle one edge's 64 features via float4 +
// vector reduction. h and acc live in L2 (12.8MB each).
__global__ __launch_bounds__(256) void k_scatter(const void* __restrict__ ei,
                                                 const float* __restrict__ ew,
                                                 int E) {
    long long gt = (long long)blockIdx.x * blockDim.x + threadIdx.x;
    int e = (int)(gt >> 4);
    int p = (int)(gt & 15);
    if (e >= E) return;
    int s = load_idx(ei, e);
    int d = load_idx(ei, (long long)E + e);
    float norm = g_dinv[s] * ew[e] * g_dinv[d];
    float4 hv = *(const float4*)(g_h + (size_t)s * HID + p * 4);
    float mx = hv.x * norm, my = hv.y * norm, mz = hv.z * norm, mw = hv.w * norm;
    float* addr = g_acc + (size_t)d * HID + p * 4;
    asm volatile("red.global.add.v4.f32 [%0], {%1,%2,%3,%4};"
                 :: "l"(addr), "f"(mx), "f"(my), "f"(mz), "f"(mw)
                 : "memory");
}

// node epilogue: self-loop + bias + tanh; write node embeddings; pool sums/cnt
__global__ void k_node_epi(const void* __restrict__ batch,
                           const float* __restrict__ b,
                           float* __restrict__ out_node, int N) {
    int total = N * HID;
    for (int i = blockIdx.x * blockDim.x + threadIdx.x; i < total;
         i += gridDim.x * blockDim.x) {
        int n = i >> 6;   // /64
        int c = i & 63;
        float dv = g_dinv[n];
        float val = g_acc[i] + g_h[i] * dv * dv + b[c];
        float t = tanhf(val);
        out_node[i] = t;
        int g = load_idx(batch, n);
        atomicAdd(&g_sums[g * HID + c], t);
        if (c == 0) atomicAdd(&g_cnt[g], 1.0f);
    }
}

// graph epilogue: mean -> @W1 + b1 -> tanh. 128 graphs x 32 outs.
__global__ void k_graph_epi(const float* __restrict__ W1,
                            const float* __restrict__ b1,
                            float* __restrict__ out_graph) {
    int tid = blockIdx.x * blockDim.x + threadIdx.x;
    if (tid >= NG * OUTF) return;
    int g = tid >> 5;   // /32
    int o = tid & 31;
    float cnt = g_cnt[g];
    float inv = 1.0f / fmaxf(cnt, 1.0f);
    float sum = b1[o];
#pragma unroll 8
    for (int k = 0; k < HID; k++)
        sum += g_sums[g * HID + k] * inv * W1[k * OUTF + o];
    out_graph[g * OUTF + o] = tanhf(sum);
}

// ---------------- launch -----------------------------------------------------

extern "C" void kernel_launch(void* const* d_in, const int* in_sizes, int n_in,
                              void* d_out, int out_size) {
    const float* x     = (const float*)d_in[0];
    const void*  ei    = d_in[1];                 // int32 or int64, detected
    const float* ew    = (const float*)d_in[2];
    const void*  batch = d_in[3];
    // d_in[4] = num_graphs (scalar) — fixed at 128
    const float* W  = (const float*)d_in[5];
    const float* b  = (const float*)d_in[6];
    const float* W1 = (const float*)d_in[7];
    const float* b1 = (const float*)d_in[8];

    int N = in_sizes[0] / INF_;   // 50000
    int E = in_sizes[2];          // 800000

    float* out_graph = (float*)d_out;              // [128, 32]
    float* out_node  = (float*)d_out + NG * OUTF;  // [N, 64]

    const int T = 256;
    k_init<<<(N * HID + T - 1) / T, T>>>(N);
    k_detect<<<1, 256>>>((const int*)ei, E);
    k_deg<<<(E + T - 1) / T, T>>>(ei, ew, E);
    k_dinv<<<(N + T - 1) / T, T>>>(N);
    k_gemm1<<<(N + 63) / 64, 256>>>(x, W, N);

    long long scatter_threads = (long long)E * 16;
    k_scatter<<<(unsigned)((scatter_threads + T - 1) / T), T>>>(ei, ew, E);

    k_node_epi<<<(N * HID + T - 1) / T, T>>>(batch, b, out_node, N);
    k_graph_epi<<<(NG * OUTF + T - 1) / T, T>>>(W1, b1, out_graph);
}

// round 2
// speedup vs baseline: 1.2487x; 1.2487x over previous
#include <cuda_runtime.h>
#include <math.h>

// ---------------- scratch (device globals; no allocation allowed) ----------
#define MAXN 50000
#define MAXE 800000
#define NG   128
#define INF_ 128
#define HID  64
#define OUTF 32
#define SCAN_BLK 256

__device__ float  g_deg[MAXN];
__device__ float  g_dinv[MAXN];
__device__ float  g_h[(size_t)MAXN * HID];     // x @ W
__device__ int    g_indeg[MAXN];               // in-degree histogram
__device__ int    g_off[MAXN];                 // CSR offsets (exclusive scan)
__device__ int    g_cursor[MAXN];              // fill cursors
__device__ float2 g_csr[MAXE];                 // (.x = bitcast src, .y = norm)
__device__ int    g_blocksum[512];
__device__ int    g_blockoff[512];
__device__ int    g_is64;

// ---------------- kernels ---------------------------------------------------

__global__ void k_init(int N) {
    for (int i = blockIdx.x * blockDim.x + threadIdx.x; i < N;
         i += gridDim.x * blockDim.x) {
        g_deg[i]   = 1.0f;   // self-loop weight
        g_indeg[i] = 0;
    }
}

// Detect whether edge_index is int64 (high 32-bit words all zero) or int32.
__global__ void k_detect(const int* __restrict__ ei_w, int E) {
    __shared__ int any_nonzero;
    if (threadIdx.x == 0) any_nonzero = 0;
    __syncthreads();
    for (int i = threadIdx.x; i < 1024; i += blockDim.x) {
        if (ei_w[2 * i + 1] != 0) atomicOr(&any_nonzero, 1);
    }
    __syncthreads();
    if (threadIdx.x == 0) g_is64 = any_nonzero ? 0 : 1;
}

__device__ __forceinline__ int load_idx(const void* p, long long i) {
    if (g_is64) return (int)((const long long*)p)[i];
    return ((const int*)p)[i];
}

// fused: weighted degree + in-degree histogram
__global__ void k_deg_hist(const void* __restrict__ ei,
                           const float* __restrict__ ew, int E) {
    int e = blockIdx.x * blockDim.x + threadIdx.x;
    if (e >= E) return;
    int d = load_idx(ei, (long long)E + e);
    atomicAdd(&g_deg[d], ew[e]);
    atomicAdd(&g_indeg[d], 1);
}

__global__ void k_dinv(int N) {
    int n = blockIdx.x * blockDim.x + threadIdx.x;
    if (n >= N) return;
    float dg = g_deg[n];
    g_dinv[n] = dg > 0.0f ? rsqrtf(dg) : 0.0f;
}

// ---- exclusive scan of g_indeg -> g_off (3 phases) ----
__global__ void k_scan_a(int N) {           // per-block sums
    __shared__ int s[SCAN_BLK];
    int i = blockIdx.x * SCAN_BLK + threadIdx.x;
    s[threadIdx.x] = (i < N) ? g_indeg[i] : 0;
    __syncthreads();
    for (int off = SCAN_BLK / 2; off > 0; off >>= 1) {
        if (threadIdx.x < off) s[threadIdx.x] += s[threadIdx.x + off];
        __syncthreads();
    }
    if (threadIdx.x == 0) g_blocksum[blockIdx.x] = s[0];
}

__global__ void k_scan_b(int nblk) {        // serial scan of block sums
    if (threadIdx.x == 0) {
        int run = 0;
        for (int b = 0; b < nblk; b++) {
            g_blockoff[b] = run;
            run += g_blocksum[b];
        }
    }
}

__global__ void k_scan_c(int N) {           // per-block exclusive scan + offset
    __shared__ int s[SCAN_BLK];
    int i = blockIdx.x * SCAN_BLK + threadIdx.x;
    int v = (i < N) ? g_indeg[i] : 0;
    s[threadIdx.x] = v;
    __syncthreads();
    for (int off = 1; off < SCAN_BLK; off <<= 1) {
        int tmp = (threadIdx.x >= off) ? s[threadIdx.x - off] : 0;
        __syncthreads();
        s[threadIdx.x] += tmp;
        __syncthreads();
    }
    if (i < N) {
        int excl = s[threadIdx.x] - v + g_blockoff[blockIdx.x];
        g_off[i]    = excl;
        g_cursor[i] = excl;
    }
}

// h = x @ W  (x: [N,128], W: [128,64]) -> g_h [N,64]
__global__ __launch_bounds__(256) void k_gemm1(const float* __restrict__ x,
                                               const float* __restrict__ W,
                                               int N) {
    __shared__ float xs[64][132];
    __shared__ float Ws[128][64];
    const int t = threadIdx.x;
    const int row0 = blockIdx.x * 64;

    for (int i = t; i < 2048; i += 256) {
        int k = i >> 4, c4 = i & 15;
        *(float4*)&Ws[k][c4 * 4] = ((const float4*)W)[i];
    }
    for (int i = t; i < 64 * 32; i += 256) {
        int r = i >> 5, k4 = i & 31;
        float4 v = make_float4(0.f, 0.f, 0.f, 0.f);
        if (row0 + r < N) v = ((const float4*)(x + (size_t)(row0 + r) * INF_))[k4];
        xs[r][k4 * 4 + 0] = v.x; xs[r][k4 * 4 + 1] = v.y;
        xs[r][k4 * 4 + 2] = v.z; xs[r][k4 * 4 + 3] = v.w;
    }
    __syncthreads();

    const int ty = t >> 4, tx = t & 15;
    float acc[4][4];
#pragma unroll
    for (int i = 0; i < 4; i++)
#pragma unroll
        for (int j = 0; j < 4; j++) acc[i][j] = 0.0f;

#pragma unroll 4
    for (int k = 0; k < 128; k++) {
        float a0 = xs[ty * 4 + 0][k];
        float a1 = xs[ty * 4 + 1][k];
        float a2 = xs[ty * 4 + 2][k];
        float a3 = xs[ty * 4 + 3][k];
        float4 w = *(float4*)&Ws[k][tx * 4];
        acc[0][0] += a0 * w.x; acc[0][1] += a0 * w.y; acc[0][2] += a0 * w.z; acc[0][3] += a0 * w.w;
        acc[1][0] += a1 * w.x; acc[1][1] += a1 * w.y; acc[1][2] += a1 * w.z; acc[1][3] += a1 * w.w;
        acc[2][0] += a2 * w.x; acc[2][1] += a2 * w.y; acc[2][2] += a2 * w.z; acc[2][3] += a2 * w.w;
        acc[3][0] += a3 * w.x; acc[3][1] += a3 * w.y; acc[3][2] += a3 * w.z; acc[3][3] += a3 * w.w;
    }
#pragma unroll
    for (int i = 0; i < 4; i++) {
        int row = row0 + ty * 4 + i;
        if (row < N) {
            float4 v = make_float4(acc[i][0], acc[i][1], acc[i][2], acc[i][3]);
            *(float4*)(g_h + (size_t)row * HID + tx * 4) = v;
        }
    }
}

// fill CSR: per edge write (src, norm) at cursor[dst]++
__global__ void k_csr_fill(const void* __restrict__ ei,
                           const float* __restrict__ ew, int E) {
    int e = blockIdx.x * blockDim.x + threadIdx.x;
    if (e >= E) return;
    int s = load_idx(ei, e);
    int d = load_idx(ei, (long long)E + e);
    float nrm = g_dinv[s] * ew[e] * g_dinv[d];
    int pos = atomicAdd(&g_cursor[d], 1);
    g_csr[pos] = make_float2(__int_as_float(s), nrm);
}

// pull-mode aggregation: one warp per node, float2 per lane (64 feats).
// Fused with self-loop + bias + tanh + node embedding write. No atomics.
__global__ __launch_bounds__(256) void k_aggregate(const float* __restrict__ b,
                                                   float* __restrict__ out_node,
                                                   int N) {
    int n = blockIdx.x * 8 + (threadIdx.x >> 5);
    int lane = threadIdx.x & 31;
    if (n >= N) return;

    int start = g_off[n];
    int deg   = g_indeg[n];
    const float2* __restrict__ h2 = (const float2*)g_h;

    float ax = 0.0f, ay = 0.0f;
    if (deg > 0) {
        float2 cw = g_csr[start];
        for (int j = start; j < start + deg; j++) {
            float2 nxt = (j + 1 < start + deg) ? g_csr[j + 1] : cw;  // prefetch
            int   s = __float_as_int(cw.x);
            float w = cw.y;
            float2 hv = h2[(size_t)s * 32 + lane];
            ax += hv.x * w;
            ay += hv.y * w;
            cw = nxt;
        }
    }
    float dv = g_dinv[n];
    float sl = dv * dv;
    float2 hn = h2[(size_t)n * 32 + lane];
    float vx = ax + hn.x * sl + b[lane * 2 + 0];
    float vy = ay + hn.y * sl + b[lane * 2 + 1];
    float2 o = make_float2(tanhf(vx), tanhf(vy));
    ((float2*)out_node)[(size_t)n * 32 + lane] = o;
}

// fused mean-pool (segmented, batch sorted) + linear + tanh. One block/graph.
__global__ __launch_bounds__(256) void k_pool_graph(
    const void* __restrict__ batch, const float* __restrict__ out_node,
    const float* __restrict__ W1, const float* __restrict__ b1,
    float* __restrict__ out_graph, int N) {
    __shared__ int s_lo, s_hi;
    __shared__ float part[4][64];
    __shared__ float mean[64];
    int g = blockIdx.x;
    int t = threadIdx.x;

    if (t == 0) {  // lower_bound(g), lower_bound(g+1)
        int lo = 0, hi = N;
        while (lo < hi) { int m = (lo + hi) >> 1; if (load_idx(batch, m) < g) lo = m + 1; else hi = m; }
        s_lo = lo;
        lo = s_lo; hi = N;
        while (lo < hi) { int m = (lo + hi) >> 1; if (load_idx(batch, m) < g + 1) lo = m + 1; else hi = m; }
        s_hi = lo;
    }
    __syncthreads();
    int lo = s_lo, hi = s_hi;
    int cnt = hi - lo;

    int col = t & 63, rg = t >> 6;   // 4 row-groups x 64 cols
    float a = 0.0f;
    for (int r = lo + rg; r < hi; r += 4)
        a += out_node[(size_t)r * HID + col];
    part[rg][col] = a;
    __syncthreads();
    if (t < 64) {
        float s = part[0][t] + part[1][t] + part[2][t] + part[3][t];
        mean[t] = s / fmaxf((float)cnt, 1.0f);
    }
    __syncthreads();
    if (t < OUTF) {
        float sum = b1[t];
#pragma unroll 8
        for (int k = 0; k < HID; k++)
            sum += mean[k] * W1[k * OUTF + t];
        out_graph[g * OUTF + t] = tanhf(sum);
    }
}

// ---------------- launch -----------------------------------------------------

extern "C" void kernel_launch(void* const* d_in, const int* in_sizes, int n_in,
                              void* d_out, int out_size) {
    const float* x     = (const float*)d_in[0];
    const void*  ei    = d_in[1];
    const float* ew    = (const float*)d_in[2];
    const void*  batch = d_in[3];
    const float* W  = (const float*)d_in[5];
    const float* b  = (const float*)d_in[6];
    const float* W1 = (const float*)d_in[7];
    const float* b1 = (const float*)d_in[8];

    int N = in_sizes[0] / INF_;   // 50000
    int E = in_sizes[2];          // 800000

    float* out_graph = (float*)d_out;
    float* out_node  = (float*)d_out + NG * OUTF;

    const int T = 256;
    int nblk_scan = (N + SCAN_BLK - 1) / SCAN_BLK;

    k_init<<<(N + T - 1) / T, T>>>(N);
    k_detect<<<1, 256>>>((const int*)ei, E);
    k_deg_hist<<<(E + T - 1) / T, T>>>(ei, ew, E);
    k_dinv<<<(N + T - 1) / T, T>>>(N);
    k_scan_a<<<nblk_scan, SCAN_BLK>>>(N);
    k_scan_b<<<1, 32>>>(nblk_scan);
    k_scan_c<<<nblk_scan, SCAN_BLK>>>(N);
    k_gemm1<<<(N + 63) / 64, 256>>>(x, W, N);
    k_csr_fill<<<(E + T - 1) / T, T>>>(ei, ew, E);
    k_aggregate<<<(N + 7) / 8, 256>>>(b, out_node, N);
    k_pool_graph<<<NG, 256>>>(batch, out_node, W1, b1, out_graph, N);
}

// round 3
// speedup vs baseline: 1.4931x; 1.1957x over previous
#include <cuda_runtime.h>
#include <math.h>

// ---------------- scratch (device globals; no allocation allowed) ----------
#define MAXN 50000
#define MAXE 800000
#define NG   128
#define INF_ 128
#define HID  64
#define OUTF 32
#define NBLK_SCAN 196   // ceil(50000/256)

__device__ float  g_deg[MAXN];
__device__ float  g_dinv[MAXN];
__device__ float  g_h[(size_t)MAXN * HID];     // x @ W
__device__ int    g_indeg[MAXN];
__device__ int    g_off[MAXN];
__device__ int    g_cursor[MAXN];
__device__ float2 g_csr[MAXE];                 // (.x = bitcast src, .y = norm)
__device__ unsigned long long g_lookback[256]; // decoupled-lookback state
__device__ int    g_gstart[NG + 1];            // graph -> first node index
__device__ float  g_sums[NG * HID];
__device__ int    g_pool_cnt[NG];
__device__ int    g_is64;

__device__ __forceinline__ int load_idx(const void* p, long long i) {
    if (g_is64) return (int)((const long long*)p)[i];
    return ((const int*)p)[i];
}

// ---------------- K1: init everything + dtype detect ------------------------
__global__ void k_prep(const int* __restrict__ ei_w, int N) {
    int i = blockIdx.x * blockDim.x + threadIdx.x;
    if (i < N) { g_deg[i] = 1.0f; g_indeg[i] = 0; }
    if (i < NG * HID) g_sums[i] = 0.0f;
    if (i < NG)       g_pool_cnt[i] = 0;
    if (i < 256)      g_lookback[i] = 0ull;
    if (blockIdx.x == 0) {
        __shared__ int any_nonzero;
        if (threadIdx.x == 0) any_nonzero = 0;
        __syncthreads();
        for (int j = threadIdx.x; j < 1024; j += blockDim.x)
            if (ei_w[2 * j + 1] != 0) atomicOr(&any_nonzero, 1);
        __syncthreads();
        if (threadIdx.x == 0) g_is64 = any_nonzero ? 0 : 1;
    }
}

// ---------------- K2: deg_hist || gemm (partitioned grid) -------------------
// blocks [0, gemm_blocks)          : h = x @ W   (FMA-pipe bound)
// blocks [gemm_blocks, gridDim.x)  : degree + in-degree histogram (L2 bound)
__global__ __launch_bounds__(256) void k_deg_gemm(
    const float* __restrict__ x, const float* __restrict__ W,
    const void* __restrict__ ei, const float* __restrict__ ew,
    int N, int E, int gemm_blocks) {
    if (blockIdx.x < gemm_blocks) {
        __shared__ float xs[64][132];
        __shared__ float Ws[128][64];
        const int t = threadIdx.x;
        const int row0 = blockIdx.x * 64;

        for (int i = t; i < 2048; i += 256) {
            int k = i >> 4, c4 = i & 15;
            *(float4*)&Ws[k][c4 * 4] = ((const float4*)W)[i];
        }
        for (int i = t; i < 64 * 32; i += 256) {
            int r = i >> 5, k4 = i & 31;
            float4 v = make_float4(0.f, 0.f, 0.f, 0.f);
            if (row0 + r < N) v = ((const float4*)(x + (size_t)(row0 + r) * INF_))[k4];
            xs[r][k4 * 4 + 0] = v.x; xs[r][k4 * 4 + 1] = v.y;
            xs[r][k4 * 4 + 2] = v.z; xs[r][k4 * 4 + 3] = v.w;
        }
        __syncthreads();

        const int ty = t >> 4, tx = t & 15;
        float acc[4][4];
#pragma unroll
        for (int i = 0; i < 4; i++)
#pragma unroll
            for (int j = 0; j < 4; j++) acc[i][j] = 0.0f;

#pragma unroll 4
        for (int k = 0; k < 128; k++) {
            float a0 = xs[ty * 4 + 0][k];
            float a1 = xs[ty * 4 + 1][k];
            float a2 = xs[ty * 4 + 2][k];
            float a3 = xs[ty * 4 + 3][k];
            float4 w = *(float4*)&Ws[k][tx * 4];
            acc[0][0] += a0 * w.x; acc[0][1] += a0 * w.y; acc[0][2] += a0 * w.z; acc[0][3] += a0 * w.w;
            acc[1][0] += a1 * w.x; acc[1][1] += a1 * w.y; acc[1][2] += a1 * w.z; acc[1][3] += a1 * w.w;
            acc[2][0] += a2 * w.x; acc[2][1] += a2 * w.y; acc[2][2] += a2 * w.z; acc[2][3] += a2 * w.w;
            acc[3][0] += a3 * w.x; acc[3][1] += a3 * w.y; acc[3][2] += a3 * w.z; acc[3][3] += a3 * w.w;
        }
#pragma unroll
        for (int i = 0; i < 4; i++) {
            int row = row0 + ty * 4 + i;
            if (row < N) {
                float4 v = make_float4(acc[i][0], acc[i][1], acc[i][2], acc[i][3]);
                *(float4*)(g_h + (size_t)row * HID + tx * 4) = v;
            }
        }
    } else {
        int tid = (blockIdx.x - gemm_blocks) * 256 + threadIdx.x;
        int stride = (gridDim.x - gemm_blocks) * 256;
        for (int e = tid; e < E; e += stride) {
            int d = load_idx(ei, (long long)E + e);
            atomicAdd(&g_deg[d], ew[e]);
            atomicAdd(&g_indeg[d], 1);
        }
    }
}

// ---------------- K3: decoupled-lookback scan + dinv + graph bounds ---------
__global__ __launch_bounds__(256) void k_scan_dinv(const void* __restrict__ batch,
                                                   int N) {
    const int bid = blockIdx.x;
    const int i = bid * 256 + threadIdx.x;
    const int lane = threadIdx.x & 31, wid = threadIdx.x >> 5;
    int v = (i < N) ? g_indeg[i] : 0;

    // block-wide inclusive scan
    int xv = v;
#pragma unroll
    for (int o = 1; o < 32; o <<= 1) {
        int y = __shfl_up_sync(0xffffffffu, xv, o);
        if (lane >= o) xv += y;
    }
    __shared__ int wsum[8];
    if (lane == 31) wsum[wid] = xv;
    __syncthreads();
    if (threadIdx.x < 32) {
        int s = (threadIdx.x < 8) ? wsum[threadIdx.x] : 0;
#pragma unroll
        for (int o = 1; o < 8; o <<= 1) {
            int y = __shfl_up_sync(0xffffffffu, s, o);
            if (lane >= o) s += y;
        }
        if (threadIdx.x < 8) wsum[threadIdx.x] = s;
    }
    __syncthreads();
    int incl = xv + (wid ? wsum[wid - 1] : 0);
    int total = wsum[7];

    __shared__ int s_excl;
    if (threadIdx.x == 0) {
        if (bid == 0) {
            atomicExch(&g_lookback[0], (2ull << 32) | (unsigned)total);
            s_excl = 0;
        } else {
            atomicExch(&g_lookback[bid], (1ull << 32) | (unsigned)total);
            int ex = 0;
            int p = bid - 1;
            while (true) {
                unsigned long long w;
                do { w = *(volatile unsigned long long*)&g_lookback[p]; }
                while ((w >> 32) == 0ull);
                if ((w >> 32) == 2ull) { ex += (int)(unsigned)w; break; }
                ex += (int)(unsigned)w;
                p--;
            }
            atomicExch(&g_lookback[bid], (2ull << 32) | (unsigned)(ex + total));
            s_excl = ex;
        }
    }
    __syncthreads();
    if (i < N) {
        int excl = s_excl + incl - v;
        g_off[i]    = excl;
        g_cursor[i] = excl;
        float dg = g_deg[i];
        g_dinv[i] = dg > 0.0f ? rsqrtf(dg) : 0.0f;
        // graph boundary extraction (batch is sorted)
        int bi = load_idx(batch, i);
        int bp = (i == 0) ? -1 : load_idx(batch, i - 1);
        for (int g = bp + 1; g <= bi; g++) g_gstart[g] = i;
        if (i == N - 1)
            for (int g = bi + 1; g <= NG; g++) g_gstart[g] = N;
    }
}

// ---------------- K4: CSR fill ----------------------------------------------
__global__ void k_csr_fill(const void* __restrict__ ei,
                           const float* __restrict__ ew, int E) {
    int e = blockIdx.x * blockDim.x + threadIdx.x;
    if (e >= E) return;
    int s = load_idx(ei, e);
    int d = load_idx(ei, (long long)E + e);
    float nrm = g_dinv[s] * ew[e] * g_dinv[d];
    int pos = atomicAdd(&g_cursor[d], 1);
    g_csr[pos] = make_float2(__int_as_float(s), nrm);
}

// ---------------- K5: pull aggregation + self-loop + bias + tanh ------------
__global__ __launch_bounds__(256) void k_aggregate(const float* __restrict__ b,
                                                   float* __restrict__ out_node,
                                                   int N) {
    int n = blockIdx.x * 8 + (threadIdx.x >> 5);
    int lane = threadIdx.x & 31;
    if (n >= N) return;

    int start = g_off[n];
    int deg   = g_indeg[n];
    const float2* __restrict__ h2 = (const float2*)g_h;

    float ax = 0.0f, ay = 0.0f;
    if (deg > 0) {
        float2 cw = g_csr[start];
        for (int j = start; j < start + deg; j++) {
            float2 nxt = (j + 1 < start + deg) ? g_csr[j + 1] : cw;
            int   s = __float_as_int(cw.x);
            float w = cw.y;
            float2 hv = h2[(size_t)s * 32 + lane];
            ax += hv.x * w;
            ay += hv.y * w;
            cw = nxt;
        }
    }
    float dv = g_dinv[n];
    float sl = dv * dv;
    float2 hn = h2[(size_t)n * 32 + lane];
    float vx = ax + hn.x * sl + b[lane * 2 + 0];
    float vy = ay + hn.y * sl + b[lane * 2 + 1];
    ((float2*)out_node)[(size_t)n * 32 + lane] = make_float2(tanhf(vx), tanhf(vy));
}

// ---------------- K6: pooled mean + linear + tanh (last block finishes) -----
__global__ __launch_bounds__(256) void k_pool(const float* __restrict__ out_node,
                                              const float* __restrict__ W1,
                                              const float* __restrict__ b1,
                                              float* __restrict__ out_graph) {
    int g = blockIdx.x >> 2;
    int chunk = blockIdx.x & 3;
    int t = threadIdx.x;
    int lo = g_gstart[g], hi = g_gstart[g + 1];

    __shared__ float part[4][64];
    int col = t & 63, rg = t >> 6;
    float a = 0.0f;
    for (int r = lo + chunk * 4 + rg; r < hi; r += 16)
        a += out_node[(size_t)r * HID + col];
    part[rg][col] = a;
    __syncthreads();
    if (t < 64) {
        float s = part[0][t] + part[1][t] + part[2][t] + part[3][t];
        if (s != 0.0f) atomicAdd(&g_sums[g * HID + t], s);
    }
    __threadfence();
    __syncthreads();

    __shared__ int s_last;
    if (t == 0) s_last = (atomicAdd(&g_pool_cnt[g], 1) == 3) ? 1 : 0;
    __syncthreads();
    if (s_last) {
        __threadfence();
        if (t < OUTF) {
            float inv = 1.0f / fmaxf((float)(hi - lo), 1.0f);
            float sum = b1[t];
#pragma unroll 8
            for (int k = 0; k < HID; k++)
                sum += (*(volatile float*)&g_sums[g * HID + k]) * inv * W1[k * OUTF + t];
            out_graph[g * OUTF + t] = tanhf(sum);
        }
    }
}

// ---------------- launch -----------------------------------------------------

extern "C" void kernel_launch(void* const* d_in, const int* in_sizes, int n_in,
                              void* d_out, int out_size) {
    const float* x     = (const float*)d_in[0];
    const void*  ei    = d_in[1];
    const float* ew    = (const float*)d_in[2];
    const void*  batch = d_in[3];
    const float* W  = (const float*)d_in[5];
    const float* b  = (const float*)d_in[6];
    const float* W1 = (const float*)d_in[7];
    const float* b1 = (const float*)d_in[8];

    int N = in_sizes[0] / INF_;   // 50000
    int E = in_sizes[2];          // 800000

    float* out_graph = (float*)d_out;
    float* out_node  = (float*)d_out + NG * OUTF;

    const int T = 256;
    int gemm_blocks = (N + 63) / 64;          // 782
    int deg_blocks  = 256;

    k_prep<<<(N + T - 1) / T, T>>>((const int*)ei, N);
    k_deg_gemm<<<gemm_blocks + deg_blocks, T>>>(x, W, ei, ew, N, E, gemm_blocks);
    k_scan_dinv<<<(N + T - 1) / T, T>>>(batch, N);
    k_csr_fill<<<(E + T - 1) / T, T>>>(ei, ew, E);
    k_aggregate<<<(N + 7) / 8, T>>>(b, out_node, N);
    k_pool<<<NG * 4, T>>>(out_node, W1, b1, out_graph);
}